// round 5
// baseline (speedup 1.0000x reference)
#include <cuda_runtime.h>
#include <cuda_fp16.h>
#include <cstdint>

// ===========================================================================
// SNN (20 steps, 2 fused Linear+LIF + feedback) on int8 mma.sync (IMMA).
// Weights as 3 int8 fixed-point limbs (d1=2^-9, d2=d1/256, d3=d2/127);
// limbs 2+3 fused via K-concat with A-side factor 127 -> 2 s32 accumulators.
// Integer GEMM is exact; trajectory matches fp32 (as fp16 2-limb did).
// ===========================================================================

#define BATCH   4096
#define DIM_D   1024
#define DIM_H1  2048
#define DIM_H2  1024
#define DIM_C   64
#define NUM_STEPS 20
#define BETA 0.9f
#define THRV 1.0f

#define D1  0.001953125f                      // 2^-9
#define ID1 512.0f
#define D2  (1.0f/131072.0f)                  // 2^-17
#define ID2 131072.0f
#define SJ  (1.0f/(127.0f*131072.0f))         // d3 = d2/127

// ---------------------------------------------------------------------------
// Device-global state / scratch
// ---------------------------------------------------------------------------
__device__ float  g_m1 [(size_t)BATCH * DIM_H1];
__device__ float  g_m2 [(size_t)BATCH * DIM_H2];
__device__ float  g_spk[(size_t)BATCH * DIM_H2];
__device__ int8_t g_s1a[(size_t)BATCH * DIM_H1];   // spikes 0/1
__device__ int8_t g_s1b[(size_t)BATCH * DIM_H1];   // spikes 0/127
__device__ int8_t g_s2a[(size_t)BATCH * DIM_H2];
__device__ int8_t g_s2b[(size_t)BATCH * DIM_H2];
__device__ int8_t g_q1a[(size_t)DIM_H1 * DIM_D];   // W1 limbs
__device__ int8_t g_q1b[(size_t)DIM_H1 * DIM_D];
__device__ int8_t g_q1c[(size_t)DIM_H1 * DIM_D];
__device__ int8_t g_q2a[(size_t)DIM_H2 * DIM_H1];  // W2 limbs
__device__ int8_t g_q2b[(size_t)DIM_H2 * DIM_H1];
__device__ int8_t g_q2c[(size_t)DIM_H2 * DIM_H1];
__device__ __half g_w1hu[(size_t)DIM_H1 * DIM_D];  // fp16 TZ weights
__device__ __half g_w1l [(size_t)DIM_H1 * DIM_D];
__device__ __half g_xh  [(size_t)BATCH * DIM_D];
__device__ __half g_xl  [(size_t)BATCH * DIM_D];
__device__ __half g_xhs [(size_t)BATCH * DIM_D];

// ---------------------------------------------------------------------------
// PTX helpers
// ---------------------------------------------------------------------------
__device__ __forceinline__ uint32_t smem_u32(const void* p) {
    uint32_t a;
    asm("{ .reg .u64 t; cvta.to.shared.u64 t, %1; cvt.u32.u64 %0, t; }"
        : "=r"(a) : "l"(p));
    return a;
}
__device__ __forceinline__ void cp16(uint32_t dst, const void* src) {
    asm volatile("cp.async.cg.shared.global [%0], [%1], 16;"
                 :: "r"(dst), "l"(__cvta_generic_to_global(src)) : "memory");
}
__device__ __forceinline__ void ldsm4(uint32_t addr, uint32_t& r0, uint32_t& r1,
                                      uint32_t& r2, uint32_t& r3) {
    asm volatile("ldmatrix.sync.aligned.m8n8.x4.shared.b16 {%0,%1,%2,%3}, [%4];"
                 : "=r"(r0), "=r"(r1), "=r"(r2), "=r"(r3) : "r"(addr));
}
__device__ __forceinline__ void imma16832(int32_t* c, const uint32_t a[4],
                                          uint32_t b0, uint32_t b1) {
    asm volatile(
        "mma.sync.aligned.m16n8k32.row.col.s32.s8.s8.s32 "
        "{%0,%1,%2,%3}, {%4,%5,%6,%7}, {%8,%9}, {%0,%1,%2,%3};"
        : "+r"(c[0]), "+r"(c[1]), "+r"(c[2]), "+r"(c[3])
        : "r"(a[0]), "r"(a[1]), "r"(a[2]), "r"(a[3]), "r"(b0), "r"(b1));
}
__device__ __forceinline__ void mma16816(float* c, const uint32_t a[4],
                                         uint32_t b0, uint32_t b1) {
    asm volatile(
        "mma.sync.aligned.m16n8k16.row.col.f32.f16.f16.f32 "
        "{%0,%1,%2,%3}, {%4,%5,%6,%7}, {%8,%9}, {%0,%1,%2,%3};"
        : "+f"(c[0]), "+f"(c[1]), "+f"(c[2]), "+f"(c[3])
        : "r"(a[0]), "r"(a[1]), "r"(a[2]), "r"(a[3]), "r"(b0), "r"(b1));
}

// ===========================================================================
// Steady-state int8 kernel: CTA 128x128, 8 warps (2m x 4n), warp 64x32.
// Flat chunk loop over 3 phases x (K/64) chunks of 64 int8 K-bytes.
//   phase 0: A = s_a (0/1),   B = Q1  -> acc0
//   phase 1: A = s_b (0/127), B = Q2  -> accJ
//   phase 2: A = s_a,         B = Q3  -> accJ
// h = 2^-9 * acc0 + (2^-17/127) * accJ + bias; fused LIF epilogue.
// smem: 4 stages x (A 128x80 + B 128x80) = 80 KB, conflict-free 80B pitch.
// ===========================================================================
#define PITCH 80
#define TILE  (128 * PITCH)
#define STAGE (2 * TILE)

template <int K, bool FIRST, bool SUM>
__global__ void __launch_bounds__(256, 1)
snn_imma(const int8_t* __restrict__ Aa, const int8_t* __restrict__ Ab,
         const int8_t* __restrict__ Q1, const int8_t* __restrict__ Q2,
         const int8_t* __restrict__ Q3, const float* __restrict__ bias,
         float* __restrict__ mem, int8_t* __restrict__ out_a,
         int8_t* __restrict__ out_b, float* __restrict__ spk_sum, int N)
{
    constexpr int NPC = K / 64;
    constexpr int TOT = 3 * NPC;
    extern __shared__ char smem[];
    const uint32_t sb = smem_u32(smem);

    const int tid = threadIdx.x, lane = tid & 31, wid = tid >> 5;
    const int wm = wid >> 2, wn = wid & 3;
    const int brow = blockIdx.y * 128, bcol = blockIdx.x * 128;

    const int8_t* Asrc[3] = { Aa + (size_t)brow * K, Ab + (size_t)brow * K,
                              Aa + (size_t)brow * K };
    const int8_t* Bsrc[3] = { Q1 + (size_t)bcol * K, Q2 + (size_t)bcol * K,
                              Q3 + (size_t)bcol * K };

    auto load_stage = [&](int ch) {
        const int st = ch & 3;
        const int ph = ch / NPC;
        const int k0 = (ch - ph * NPC) * 64;
        const int8_t* As = Asrc[ph];
        const int8_t* Bs = Bsrc[ph];
        const uint32_t s0 = sb + st * STAGE;
#pragma unroll
        for (int i = 0; i < 2; i++) {
            int q = tid + i * 256;          // 0..511
            int r = q >> 2, c = q & 3;
            cp16(s0 + r * PITCH + c * 16, As + (size_t)r * K + k0 + c * 16);
            cp16(s0 + TILE + r * PITCH + c * 16, Bs + (size_t)r * K + k0 + c * 16);
        }
        asm volatile("cp.async.commit_group;" ::: "memory");
    };

    // ldmatrix lane geometry (16 rows x 2 16B-cols per x4)
    const int lrow = (lane & 7) + 8 * ((lane >> 3) & 1);
    const int lcol = (lane >> 4) * 16;
    const uint32_t a_off = (uint32_t)(wm * 64 + lrow) * PITCH + lcol;
    const uint32_t b_off = TILE + (uint32_t)(wn * 32 + lrow) * PITCH + lcol;

    int32_t acc0[4][4][4], accJ[4][4][4];
#pragma unroll
    for (int i = 0; i < 4; i++)
#pragma unroll
        for (int j = 0; j < 4; j++)
#pragma unroll
            for (int k = 0; k < 4; k++) { acc0[i][j][k] = 0; accJ[i][j][k] = 0; }

    load_stage(0); load_stage(1); load_stage(2);

#define CHUNK_COMPUTE(ACC)                                                     \
    _Pragma("unroll")                                                          \
    for (int kk = 0; kk < 2; kk++) {                                           \
        uint32_t a[4][4];                                                      \
        _Pragma("unroll")                                                      \
        for (int mf = 0; mf < 4; mf++)                                         \
            ldsm4(s0 + a_off + mf * (16 * PITCH) + kk * 32,                    \
                  a[mf][0], a[mf][1], a[mf][2], a[mf][3]);                     \
        uint32_t b0[4], b1[4];                                                 \
        _Pragma("unroll")                                                      \
        for (int nh = 0; nh < 2; nh++)                                         \
            ldsm4(s0 + b_off + nh * (16 * PITCH) + kk * 32,                    \
                  b0[2 * nh], b0[2 * nh + 1], b1[2 * nh], b1[2 * nh + 1]);     \
        _Pragma("unroll")                                                      \
        for (int mf = 0; mf < 4; mf++)                                         \
            _Pragma("unroll")                                                  \
            for (int j = 0; j < 4; j++)                                        \
                imma16832(ACC[mf][j], a[mf], b0[j], b1[j]);                    \
    }

    for (int ch = 0; ch < TOT; ch++) {
        asm volatile("cp.async.wait_group 2;" ::: "memory");
        __syncthreads();
        if (ch + 3 < TOT) load_stage(ch + 3);
        else asm volatile("cp.async.commit_group;" ::: "memory");

        const uint32_t s0 = sb + (ch & 3) * STAGE;
        if (ch / NPC == 0) { CHUNK_COMPUTE(acc0) }
        else               { CHUNK_COMPUTE(accJ) }
    }
#undef CHUNK_COMPUTE

    // ---- Fused LIF epilogue ----
    const int qr = lane >> 2, qc = (lane & 3) * 2;
#pragma unroll
    for (int mf = 0; mf < 4; mf++)
#pragma unroll
    for (int h2 = 0; h2 < 2; h2++) {
        const int row = brow + wm * 64 + mf * 16 + qr + 8 * h2;
#pragma unroll
        for (int nf = 0; nf < 4; nf++) {
            const int col = bcol + wn * 32 + nf * 8 + qc;
            const size_t ix = (size_t)row * N + col;
            float2 bb = *reinterpret_cast<const float2*>(bias + col);
            float h0 = fmaf((float)acc0[mf][nf][2 * h2 + 0], D1,
                       fmaf((float)accJ[mf][nf][2 * h2 + 0], SJ, bb.x));
            float h1 = fmaf((float)acc0[mf][nf][2 * h2 + 1], D1,
                       fmaf((float)accJ[mf][nf][2 * h2 + 1], SJ, bb.y));
            float m0, m1v;
            if (FIRST) {
                m0 = h0; m1v = h1;
            } else {
                float2 mo = *reinterpret_cast<const float2*>(mem + ix);
                m0  = BETA * mo.x + h0 - ((mo.x > THRV) ? THRV : 0.0f);
                m1v = BETA * mo.y + h1 - ((mo.y > THRV) ? THRV : 0.0f);
            }
            const bool sp0 = m0 > THRV, sp1 = m1v > THRV;
            *reinterpret_cast<float2*>(mem + ix) = make_float2(m0, m1v);
            *reinterpret_cast<uint16_t*>(out_a + ix) =
                (uint16_t)((sp0 ? 1u : 0u) | ((sp1 ? 1u : 0u) << 8));
            *reinterpret_cast<uint16_t*>(out_b + ix) =
                (uint16_t)((sp0 ? 127u : 0u) | ((sp1 ? 127u : 0u) << 8));
            if (SUM) {
                float a0 = sp0 ? 1.0f : 0.0f, a1 = sp1 ? 1.0f : 0.0f;
                float2* ss = reinterpret_cast<float2*>(spk_sum + ix);
                if (FIRST) *ss = make_float2(a0, a1);
                else { float2 o = *ss; *ss = make_float2(o.x + a0, o.y + a1); }
            }
        }
    }
}

// ===========================================================================
// t=0 layer-1 (real-valued x): fp16 3-product kernel, writes int8 spikes.
// ===========================================================================
__global__ void __launch_bounds__(256, 2)
snn_tz(const __half* __restrict__ A0, const __half* __restrict__ A1,
       const __half* __restrict__ A2,
       const __half* __restrict__ W0, const __half* __restrict__ W1,
       const float* __restrict__ bias, float* __restrict__ mem,
       int8_t* __restrict__ out_a, int8_t* __restrict__ out_b, int N, int K)
{
    constexpr int FT = 16384;
    constexpr int FSTAGE = 5 * FT;
    extern __shared__ char smem[];
    const uint32_t sb = smem_u32(smem);

    const int tid = threadIdx.x, lane = tid & 31, wid = tid >> 5;
    const int wm = wid >> 2, wn = wid & 3;
    const int brow = blockIdx.y * 128, bcol = blockIdx.x * 128;

    const __half* Ap[3] = { A0 + (size_t)brow * K, A1 + (size_t)brow * K,
                            A2 + (size_t)brow * K };
    const __half* Wp[2] = { W0 + (size_t)bcol * K, W1 + (size_t)bcol * K };

    auto load_stage = [&](int st, int k0) {
        const uint32_t s0 = sb + st * FSTAGE;
#pragma unroll
        for (int l = 0; l < 3; l++) {
            const uint32_t d = s0 + l * FT;
            for (int q = tid; q < 1024; q += 256) {
                int r = q >> 3, c = q & 7;
                cp16(d + r * 128 + ((c ^ (r & 7)) << 4),
                     Ap[l] + (size_t)r * K + k0 + c * 8);
            }
        }
#pragma unroll
        for (int l = 0; l < 2; l++) {
            const uint32_t d = s0 + (3 + l) * FT;
            for (int q = tid; q < 1024; q += 256) {
                int r = q >> 3, c = q & 7;
                cp16(d + r * 128 + ((c ^ (r & 7)) << 4),
                     Wp[l] + (size_t)r * K + k0 + c * 8);
            }
        }
        asm volatile("cp.async.commit_group;" ::: "memory");
    };

    const int arow = (lane & 7) + 8 * ((lane >> 3) & 1);
    const int asel = lane >> 4;
    const int brw  = (lane & 7) + 8 * (lane >> 4);
    const int bsel = (lane >> 3) & 1;
    const int sx   = lane & 7;

    float acc[4][4][4];
#pragma unroll
    for (int i = 0; i < 4; i++)
#pragma unroll
        for (int j = 0; j < 4; j++)
#pragma unroll
            for (int k = 0; k < 4; k++) acc[i][j][k] = 0.0f;

    const int nch = K / 64;
    load_stage(0, 0);

    for (int ch = 0; ch < nch; ch++) {
        asm volatile("cp.async.wait_group 0;" ::: "memory");
        __syncthreads();
        if (ch + 1 < nch) load_stage((ch + 1) & 1, (ch + 1) * 64);

        const uint32_t s0 = sb + (ch & 1) * FSTAGE;
#pragma unroll
        for (int ks = 0; ks < 4; ks++) {
            const uint32_t aoff = ((2 * ks + asel) ^ sx) << 4;
            const uint32_t boff = ((2 * ks + bsel) ^ sx) << 4;
            uint32_t b[2][8];
#pragma unroll
            for (int w = 0; w < 2; w++) {
                const uint32_t bw = s0 + (3 + w) * FT + (wn * 32 + brw) * 128 + boff;
                ldsm4(bw, b[w][0], b[w][1], b[w][2], b[w][3]);
                ldsm4(bw + 16 * 128, b[w][4], b[w][5], b[w][6], b[w][7]);
            }
            const int PA[3] = {0, 1, 2}, PW[3] = {0, 1, 0};
#pragma unroll
            for (int p = 0; p < 3; p++) {
                uint32_t a[4][4];
#pragma unroll
                for (int mf = 0; mf < 4; mf++)
                    ldsm4(s0 + PA[p] * FT + (wm * 64 + mf * 16 + arow) * 128 + aoff,
                          a[mf][0], a[mf][1], a[mf][2], a[mf][3]);
#pragma unroll
                for (int mf = 0; mf < 4; mf++)
#pragma unroll
                    for (int nf = 0; nf < 4; nf++)
                        mma16816(acc[mf][nf], a[mf], b[PW[p]][2 * nf], b[PW[p]][2 * nf + 1]);
            }
        }
        __syncthreads();
    }

    const int qr = lane >> 2, qc = (lane & 3) * 2;
#pragma unroll
    for (int mf = 0; mf < 4; mf++)
#pragma unroll
    for (int h2 = 0; h2 < 2; h2++) {
        const int row = brow + wm * 64 + mf * 16 + qr + 8 * h2;
#pragma unroll
        for (int nf = 0; nf < 4; nf++) {
            const int col = bcol + wn * 32 + nf * 8 + qc;
            const size_t ix = (size_t)row * N + col;
            float2 bb = *reinterpret_cast<const float2*>(bias + col);
            float m0  = acc[mf][nf][2 * h2 + 0] + bb.x;
            float m1v = acc[mf][nf][2 * h2 + 1] + bb.y;
            const bool sp0 = m0 > THRV, sp1 = m1v > THRV;
            *reinterpret_cast<float2*>(mem + ix) = make_float2(m0, m1v);
            *reinterpret_cast<uint16_t*>(out_a + ix) =
                (uint16_t)((sp0 ? 1u : 0u) | ((sp1 ? 1u : 0u) << 8));
            *reinterpret_cast<uint16_t*>(out_b + ix) =
                (uint16_t)((sp0 ? 127u : 0u) | ((sp1 ? 127u : 0u) << 8));
        }
    }
}

// ---------------------------------------------------------------------------
// Weight quantization to 3 int8 limbs (exact residual capture, see header).
// ---------------------------------------------------------------------------
__global__ void __launch_bounds__(256)
quant_w(const float* __restrict__ w, int8_t* __restrict__ qa,
        int8_t* __restrict__ qb, int8_t* __restrict__ qc_, int n)
{
    for (int i = blockIdx.x * 256 + threadIdx.x; i < n; i += gridDim.x * 256) {
        float v = w[i];
        float f1 = fminf(fmaxf(rintf(v * ID1), -127.0f), 127.0f);
        float r1 = v - f1 * D1;
        float f2 = fminf(fmaxf(rintf(r1 * ID2), -127.0f), 127.0f);
        float r2 = r1 - f2 * D2;
        float f3 = fminf(fmaxf(rintf(r2 * (ID2 * 127.0f)), -127.0f), 127.0f);
        qa[i] = (int8_t)f1; qb[i] = (int8_t)f2; qc_[i] = (int8_t)f3;
    }
}

// fp16 splits for the t=0 kernel
__global__ void __launch_bounds__(256)
split_w1(const float* __restrict__ w, __half* __restrict__ hu,
         __half* __restrict__ l, int n)
{
    for (int i = blockIdx.x * 256 + threadIdx.x; i < n; i += gridDim.x * 256) {
        float v = w[i] * 2048.0f;
        __half h = __float2half_rn(v);
        l[i]  = __float2half_rn(v - __half2float(h));
        hu[i] = __float2half_rn(__half2float(h) * (1.0f / 2048.0f));
    }
}
__global__ void __launch_bounds__(256)
split_x(const float* __restrict__ x, __half* __restrict__ xh,
        __half* __restrict__ xl, __half* __restrict__ xhs, int n)
{
    for (int i = blockIdx.x * 256 + threadIdx.x; i < n; i += gridDim.x * 256) {
        float v = x[i];
        __half h = __float2half_rn(v);
        xh[i] = h;
        xl[i] = __float2half_rn(v - __half2float(h));
        xhs[i] = __float2half_rn(__half2float(h) * (1.0f / 2048.0f));
    }
}

__global__ void __launch_bounds__(256)
snn_readout(const float* __restrict__ spk_sum, const float* __restrict__ Wo,
            const float* __restrict__ bo, float* __restrict__ out)
{
    const int c  = threadIdx.x & 63;
    const int r4 = threadIdx.x >> 6;
    const size_t b = (size_t)blockIdx.x * 4 + r4;
    const float* s = spk_sum + b * DIM_H2;
    const float* w = Wo + (size_t)c * DIM_H2;
    float acc = 0.0f;
#pragma unroll 4
    for (int k = 0; k < DIM_H2; k += 4) {
        float4 sv = *reinterpret_cast<const float4*>(s + k);
        float4 wv = *reinterpret_cast<const float4*>(w + k);
        acc = fmaf(sv.x, wv.x, acc);
        acc = fmaf(sv.y, wv.y, acc);
        acc = fmaf(sv.z, wv.z, acc);
        acc = fmaf(sv.w, wv.w, acc);
    }
    out[b * DIM_C + c] = acc * (1.0f / (float)NUM_STEPS) + bo[c];
}

// ---------------------------------------------------------------------------
extern "C" void kernel_launch(void* const* d_in, const int* in_sizes, int n_in,
                              void* d_out, int out_size)
{
    const float* x  = (const float*)d_in[0];
    const float* W1 = (const float*)d_in[1];
    const float* b1 = (const float*)d_in[2];
    const float* W2 = (const float*)d_in[3];
    const float* b2 = (const float*)d_in[4];
    const float* Wo = (const float*)d_in[5];
    const float* bo = (const float*)d_in[6];
    float* out = (float*)d_out;

    auto sym = [](const void* s) { void* p; cudaGetSymbolAddress(&p, s); return p; };
    float*  m1  = (float*)sym(g_m1);
    float*  m2  = (float*)sym(g_m2);
    float*  spk = (float*)sym(g_spk);
    int8_t* s1a = (int8_t*)sym(g_s1a);
    int8_t* s1b = (int8_t*)sym(g_s1b);
    int8_t* s2a = (int8_t*)sym(g_s2a);
    int8_t* s2b = (int8_t*)sym(g_s2b);
    int8_t* q1a = (int8_t*)sym(g_q1a);
    int8_t* q1b = (int8_t*)sym(g_q1b);
    int8_t* q1c = (int8_t*)sym(g_q1c);
    int8_t* q2a = (int8_t*)sym(g_q2a);
    int8_t* q2b = (int8_t*)sym(g_q2b);
    int8_t* q2c = (int8_t*)sym(g_q2c);
    __half* w1hu = (__half*)sym(g_w1hu);
    __half* w1l  = (__half*)sym(g_w1l);
    __half* xh   = (__half*)sym(g_xh);
    __half* xl   = (__half*)sym(g_xl);
    __half* xhs  = (__half*)sym(g_xhs);

    constexpr int SM_I = 4 * STAGE;        // 81920
    constexpr int SM_TZ = 2 * 5 * 16384;   // 163840
    cudaFuncSetAttribute(snn_tz, cudaFuncAttributeMaxDynamicSharedMemorySize, SM_TZ);
    cudaFuncSetAttribute(snn_imma<DIM_H1, true,  true >, cudaFuncAttributeMaxDynamicSharedMemorySize, SM_I);
    cudaFuncSetAttribute(snn_imma<DIM_H2, false, false>, cudaFuncAttributeMaxDynamicSharedMemorySize, SM_I);
    cudaFuncSetAttribute(snn_imma<DIM_H1, false, true >, cudaFuncAttributeMaxDynamicSharedMemorySize, SM_I);

    quant_w <<<2048, 256>>>(W1, q1a, q1b, q1c, DIM_H1 * DIM_D);
    quant_w <<<2048, 256>>>(W2, q2a, q2b, q2c, DIM_H2 * DIM_H1);
    split_w1<<<2048, 256>>>(W1, w1hu, w1l, DIM_H1 * DIM_D);
    split_x <<<2048, 256>>>(x, xh, xl, xhs, BATCH * DIM_D);

    dim3 blk(256);
    dim3 gtz(DIM_H1 / 128, BATCH / 128);   // (16, 32)
    dim3 g1 (DIM_H1 / 128, BATCH / 128);   // (16, 32)
    dim3 g2 (DIM_H2 / 128, BATCH / 128);   // (8, 32)

    // t = 0
    snn_tz<<<gtz, blk, SM_TZ>>>(xh, xhs, xl, w1hu, w1l, b1, m1, s1a, s1b,
                                DIM_H1, DIM_D);
    snn_imma<DIM_H1, true, true><<<g2, blk, SM_I>>>(
        s1a, s1b, q2a, q2b, q2c, b2, m2, s2a, s2b, spk, DIM_H2);

    for (int t = 1; t < NUM_STEPS; t++) {
        snn_imma<DIM_H2, false, false><<<g1, blk, SM_I>>>(
            s2a, s2b, q1a, q1b, q1c, b1, m1, s1a, s1b, nullptr, DIM_H1);
        snn_imma<DIM_H1, false, true><<<g2, blk, SM_I>>>(
            s1a, s1b, q2a, q2b, q2c, b2, m2, s2a, s2b, spk, DIM_H2);
    }

    snn_readout<<<BATCH / 4, blk>>>(spk, Wo, bo, out);
}

// round 6
// speedup vs baseline: 1.4249x; 1.4249x over previous
#include <cuda_runtime.h>
#include <cuda_fp16.h>
#include <cstdint>

// ===========================================================================
// SNN (20 steps, 2 fused Linear+LIF layers + feedback) on mma.sync (HMMA).
// Spikes stored as exactly 2^-11, weights split into 2 fp16 limbs scaled by
// 2^11 -> products exact, residual ~|w|*2^-24 (fp32-identical trajectory).
// Round 6: revert to the round-3 configuration (best known: 5291us, ~92% of
// the legacy-HMMA 1024 MAC/cyc/SM cap) + fused prep kernel.
// ===========================================================================

#define BATCH   4096
#define DIM_D   1024
#define DIM_H1  2048
#define DIM_H2  1024
#define DIM_C   64
#define NUM_STEPS 20
#define BETA 0.9f
#define THRV 1.0f

// ---------------------------------------------------------------------------
// Device-global state / scratch
// ---------------------------------------------------------------------------
__device__ float  g_m1 [(size_t)BATCH * DIM_H1];
__device__ float  g_m2 [(size_t)BATCH * DIM_H2];
__device__ float  g_spk[(size_t)BATCH * DIM_H2];
__device__ __half g_s1 [(size_t)BATCH * DIM_H1];
__device__ __half g_s2 [(size_t)BATCH * DIM_H2];
__device__ __half g_w1h [(size_t)DIM_H1 * DIM_D];   // W1 * 2^11, hi limb
__device__ __half g_w1l [(size_t)DIM_H1 * DIM_D];   // W1 * 2^11, lo limb
__device__ __half g_w1hu[(size_t)DIM_H1 * DIM_D];   // W1 hi limb, unscaled (t=0)
__device__ __half g_w2h [(size_t)DIM_H2 * DIM_H1];
__device__ __half g_w2l [(size_t)DIM_H2 * DIM_H1];
__device__ __half g_xh  [(size_t)BATCH * DIM_D];    // fp16(x)
__device__ __half g_xl  [(size_t)BATCH * DIM_D];    // fp16(x - xh)
__device__ __half g_xhs [(size_t)BATCH * DIM_D];    // fp16(xh * 2^-11)

// ---------------------------------------------------------------------------
// PTX helpers (sm_80-era: cp.async / ldmatrix / mma.sync -> compile for sm_100)
// ---------------------------------------------------------------------------
__device__ __forceinline__ uint32_t smem_u32(const void* p) {
    uint32_t a;
    asm("{ .reg .u64 t; cvta.to.shared.u64 t, %1; cvt.u32.u64 %0, t; }"
        : "=r"(a) : "l"(p));
    return a;
}
__device__ __forceinline__ void cp16(uint32_t dst, const void* src) {
    asm volatile("cp.async.cg.shared.global [%0], [%1], 16;"
                 :: "r"(dst), "l"(__cvta_generic_to_global(src)) : "memory");
}
__device__ __forceinline__ void ldsm4(uint32_t addr, uint32_t& r0, uint32_t& r1,
                                      uint32_t& r2, uint32_t& r3) {
    asm volatile("ldmatrix.sync.aligned.m8n8.x4.shared.b16 {%0,%1,%2,%3}, [%4];"
                 : "=r"(r0), "=r"(r1), "=r"(r2), "=r"(r3) : "r"(addr));
}
__device__ __forceinline__ void mma16816(float* c, const uint32_t a[4],
                                         uint32_t b0, uint32_t b1) {
    asm volatile(
        "mma.sync.aligned.m16n8k16.row.col.f32.f16.f16.f32 "
        "{%0,%1,%2,%3}, {%4,%5,%6,%7}, {%8,%9}, {%0,%1,%2,%3};"
        : "+f"(c[0]), "+f"(c[1]), "+f"(c[2]), "+f"(c[3])
        : "r"(a[0]), "r"(a[1]), "r"(a[2]), "r"(a[3]), "r"(b0), "r"(b1));
}

// ---------------------------------------------------------------------------
// Fused GEMM + LIF.  D[row,col] = sum_k A[row,k] * W[col,k]  (+ limb products)
// TZ=false: A=spikes(2^-11), products (A,W0)+(A,W1), W limbs scaled 2^11.
// TZ=true : A limbs {xh, xh*2^-11, xl}, products (0,W0),(1,W1),(2,W0),
//           W0 = unscaled hi limb, W1 = lo limb * 2^11.
// 128x128 CTA tile, 8 warps (2m x 4n), warp tile 64x32, BK=64, 2 stages.
// ---------------------------------------------------------------------------
template <bool TZ, bool FIRST, bool SUM>
__global__ void __launch_bounds__(256, 2)
snn_hmma(const __half* __restrict__ A0, const __half* __restrict__ A1,
         const __half* __restrict__ A2,
         const __half* __restrict__ W0, const __half* __restrict__ W1,
         const float* __restrict__ bias, float* __restrict__ mem,
         __half* __restrict__ spk, float* __restrict__ spk_sum,
         int N, int K)
{
    constexpr int NA = TZ ? 3 : 1;
    constexpr int TILE = 16384;                 // 128 rows x 128 bytes
    constexpr int STAGE = (NA + 2) * TILE;
    extern __shared__ char smem[];
    const uint32_t sb = smem_u32(smem);

    const int tid = threadIdx.x, lane = tid & 31, wid = tid >> 5;
    const int wm = wid >> 2, wn = wid & 3;
    const int brow = blockIdx.y * 128, bcol = blockIdx.x * 128;

    const __half* Ap[3];
    Ap[0] = A0 + (size_t)brow * K;
    Ap[1] = TZ ? A1 + (size_t)brow * K : Ap[0];
    Ap[2] = TZ ? A2 + (size_t)brow * K : Ap[0];
    const __half* Wp[2] = { W0 + (size_t)bcol * K, W1 + (size_t)bcol * K };

    auto load_stage = [&](int st, int k0) {
        const uint32_t s0 = sb + st * STAGE;
#pragma unroll
        for (int l = 0; l < NA; l++) {
            const __half* g = Ap[l];
            const uint32_t d = s0 + l * TILE;
            for (int q = tid; q < 1024; q += 256) {
                int r = q >> 3, c = q & 7;
                cp16(d + r * 128 + ((c ^ (r & 7)) << 4),
                     g + (size_t)r * K + k0 + c * 8);
            }
        }
#pragma unroll
        for (int l = 0; l < 2; l++) {
            const __half* g = Wp[l];
            const uint32_t d = s0 + (NA + l) * TILE;
            for (int q = tid; q < 1024; q += 256) {
                int r = q >> 3, c = q & 7;
                cp16(d + r * 128 + ((c ^ (r & 7)) << 4),
                     g + (size_t)r * K + k0 + c * 8);
            }
        }
        asm volatile("cp.async.commit_group;" ::: "memory");
    };

    // ldmatrix lane geometry
    const int arow = (lane & 7) + 8 * ((lane >> 3) & 1);   // A: m within 16
    const int asel = lane >> 4;                            // A: k-chunk select
    const int brw  = (lane & 7) + 8 * (lane >> 4);         // B: n within 16
    const int bsel = (lane >> 3) & 1;                      // B: k-chunk select
    const int sx   = lane & 7;                             // swizzle key

    float acc[4][4][4];
#pragma unroll
    for (int i = 0; i < 4; i++)
#pragma unroll
        for (int j = 0; j < 4; j++)
#pragma unroll
            for (int k = 0; k < 4; k++) acc[i][j][k] = 0.0f;

    const int nch = K / 64;
    load_stage(0, 0);

    for (int ch = 0; ch < nch; ch++) {
        if (ch + 1 < nch) {
            load_stage((ch + 1) & 1, (ch + 1) * 64);
            asm volatile("cp.async.wait_group 1;" ::: "memory");
        } else {
            asm volatile("cp.async.wait_group 0;" ::: "memory");
        }
        __syncthreads();

        const uint32_t s0 = sb + (ch & 1) * STAGE;
        uint32_t bb[2][2];
#pragma unroll
        for (int w = 0; w < 2; w++)
#pragma unroll
            for (int h = 0; h < 2; h++)
                bb[w][h] = s0 + (NA + w) * TILE + (wn * 32 + h * 16 + brw) * 128;

#pragma unroll
        for (int ks = 0; ks < 4; ks++) {
            uint32_t b[2][8];
#pragma unroll
            for (int w = 0; w < 2; w++) {
                const uint32_t off = ((2 * ks + bsel) ^ sx) << 4;
                ldsm4(bb[w][0] + off, b[w][0], b[w][1], b[w][2], b[w][3]);
                ldsm4(bb[w][1] + off, b[w][4], b[w][5], b[w][6], b[w][7]);
            }
            const uint32_t aoff = ((2 * ks + asel) ^ sx) << 4;
            if (!TZ) {
                uint32_t a[4][4];
#pragma unroll
                for (int mf = 0; mf < 4; mf++)
                    ldsm4(s0 + (wm * 64 + mf * 16 + arow) * 128 + aoff,
                          a[mf][0], a[mf][1], a[mf][2], a[mf][3]);
#pragma unroll
                for (int w = 0; w < 2; w++)
#pragma unroll
                    for (int mf = 0; mf < 4; mf++)
#pragma unroll
                        for (int nf = 0; nf < 4; nf++)
                            mma16816(acc[mf][nf], a[mf], b[w][2 * nf], b[w][2 * nf + 1]);
            } else {
                const int PA[3] = {0, 1, 2}, PW[3] = {0, 1, 0};
#pragma unroll
                for (int p = 0; p < 3; p++) {
                    uint32_t a[4][4];
#pragma unroll
                    for (int mf = 0; mf < 4; mf++)
                        ldsm4(s0 + PA[p] * TILE + (wm * 64 + mf * 16 + arow) * 128 + aoff,
                              a[mf][0], a[mf][1], a[mf][2], a[mf][3]);
#pragma unroll
                    for (int mf = 0; mf < 4; mf++)
#pragma unroll
                        for (int nf = 0; nf < 4; nf++)
                            mma16816(acc[mf][nf], a[mf], b[PW[p]][2 * nf], b[PW[p]][2 * nf + 1]);
                }
            }
        }
        __syncthreads();
    }

    // ---- Fused LIF epilogue on register accumulators ----
    const int qr = lane >> 2, qc = (lane & 3) * 2;
#pragma unroll
    for (int mf = 0; mf < 4; mf++)
#pragma unroll
    for (int h = 0; h < 2; h++) {
        const int row = brow + wm * 64 + mf * 16 + qr + 8 * h;
#pragma unroll
        for (int nf = 0; nf < 4; nf++) {
            const int col = bcol + wn * 32 + nf * 8 + qc;
            const size_t ix = (size_t)row * N + col;
            float2 bb = *reinterpret_cast<const float2*>(bias + col);
            float v0 = acc[mf][nf][2 * h + 0] + bb.x;
            float v1 = acc[mf][nf][2 * h + 1] + bb.y;
            float m0, m1v;
            if (FIRST) {
                m0 = v0; m1v = v1;
            } else {
                float2 mo = *reinterpret_cast<const float2*>(mem + ix);
                m0  = BETA * mo.x + v0 - ((mo.x > THRV) ? THRV : 0.0f);
                m1v = BETA * mo.y + v1 - ((mo.y > THRV) ? THRV : 0.0f);
            }
            const bool sp0 = m0 > THRV, sp1 = m1v > THRV;
            *reinterpret_cast<float2*>(mem + ix) = make_float2(m0, m1v);
            // spike value = 2^-11 exactly (fp16 bits 0x1000)
            uint32_t sv = (sp0 ? 0x1000u : 0u) | (sp1 ? 0x10000000u : 0u);
            *reinterpret_cast<uint32_t*>(spk + ix) = sv;
            if (SUM) {
                float a0 = sp0 ? 1.0f : 0.0f, a1 = sp1 ? 1.0f : 0.0f;
                float2* ss = reinterpret_cast<float2*>(spk_sum + ix);
                if (FIRST) {
                    *ss = make_float2(a0, a1);
                } else {
                    float2 o = *ss;
                    *ss = make_float2(o.x + a0, o.y + a1);
                }
            }
        }
    }
}

// ---------------------------------------------------------------------------
// Fused prep: one launch covers W1 split (3 outs), W2 split (2 outs),
// x split (3 outs). Segmented by flat index.
// ---------------------------------------------------------------------------
#define N_W1 (DIM_H1 * DIM_D)
#define N_W2 (DIM_H2 * DIM_H1)
#define N_X  (BATCH * DIM_D)

__global__ void __launch_bounds__(256)
prep_all(const float* __restrict__ W1, const float* __restrict__ W2,
         const float* __restrict__ x,
         __half* __restrict__ w1h, __half* __restrict__ w1l,
         __half* __restrict__ w1hu,
         __half* __restrict__ w2h, __half* __restrict__ w2l,
         __half* __restrict__ xh, __half* __restrict__ xl,
         __half* __restrict__ xhs)
{
    const int total = N_W1 + N_W2 + N_X;
    for (int i = blockIdx.x * 256 + threadIdx.x; i < total; i += gridDim.x * 256) {
        if (i < N_W1) {
            float v = W1[i] * 2048.0f;
            __half h = __float2half_rn(v);
            w1h[i] = h;
            w1l[i] = __float2half_rn(v - __half2float(h));
            w1hu[i] = __float2half_rn(__half2float(h) * (1.0f / 2048.0f));
        } else if (i < N_W1 + N_W2) {
            int j = i - N_W1;
            float v = W2[j] * 2048.0f;
            __half h = __float2half_rn(v);
            w2h[j] = h;
            w2l[j] = __float2half_rn(v - __half2float(h));
        } else {
            int j = i - N_W1 - N_W2;
            float v = x[j];
            __half h = __float2half_rn(v);
            xh[j] = h;
            xl[j] = __float2half_rn(v - __half2float(h));
            xhs[j] = __float2half_rn(__half2float(h) * (1.0f / 2048.0f));
        }
    }
}

// ---------------------------------------------------------------------------
// Readout: out[b,c] = (spk_sum[b,:]/NUM_STEPS) . Wo[c,:] + bo[c]
// ---------------------------------------------------------------------------
__global__ void __launch_bounds__(256)
snn_readout(const float* __restrict__ spk_sum, const float* __restrict__ Wo,
            const float* __restrict__ bo, float* __restrict__ out)
{
    const int c  = threadIdx.x & 63;
    const int r4 = threadIdx.x >> 6;
    const size_t b = (size_t)blockIdx.x * 4 + r4;
    const float* s = spk_sum + b * DIM_H2;
    const float* w = Wo + (size_t)c * DIM_H2;
    float acc = 0.0f;
#pragma unroll 4
    for (int k = 0; k < DIM_H2; k += 4) {
        float4 sv = *reinterpret_cast<const float4*>(s + k);
        float4 wv = *reinterpret_cast<const float4*>(w + k);
        acc = fmaf(sv.x, wv.x, acc);
        acc = fmaf(sv.y, wv.y, acc);
        acc = fmaf(sv.z, wv.z, acc);
        acc = fmaf(sv.w, wv.w, acc);
    }
    out[b * DIM_C + c] = acc * (1.0f / (float)NUM_STEPS) + bo[c];
}

// ---------------------------------------------------------------------------
extern "C" void kernel_launch(void* const* d_in, const int* in_sizes, int n_in,
                              void* d_out, int out_size)
{
    const float* x  = (const float*)d_in[0];
    const float* W1 = (const float*)d_in[1];
    const float* b1 = (const float*)d_in[2];
    const float* W2 = (const float*)d_in[3];
    const float* b2 = (const float*)d_in[4];
    const float* Wo = (const float*)d_in[5];
    const float* bo = (const float*)d_in[6];
    float* out = (float*)d_out;

    auto sym = [](const void* s) { void* p; cudaGetSymbolAddress(&p, s); return p; };
    float*  m1   = (float*)sym(g_m1);
    float*  m2   = (float*)sym(g_m2);
    float*  spk  = (float*)sym(g_spk);
    __half* s1   = (__half*)sym(g_s1);
    __half* s2   = (__half*)sym(g_s2);
    __half* w1h  = (__half*)sym(g_w1h);
    __half* w1l  = (__half*)sym(g_w1l);
    __half* w1hu = (__half*)sym(g_w1hu);
    __half* w2h  = (__half*)sym(g_w2h);
    __half* w2l  = (__half*)sym(g_w2l);
    __half* xh   = (__half*)sym(g_xh);
    __half* xl   = (__half*)sym(g_xl);
    __half* xhs  = (__half*)sym(g_xhs);

    constexpr int SM_STD = 2 * 3 * 16384;   //  98304 B -> 2 CTA/SM
    constexpr int SM_TZ  = 2 * 5 * 16384;   // 163840 B -> 1 CTA/SM (runs once)
    cudaFuncSetAttribute(snn_hmma<true,  true,  false>, cudaFuncAttributeMaxDynamicSharedMemorySize, SM_TZ);
    cudaFuncSetAttribute(snn_hmma<false, true,  true >, cudaFuncAttributeMaxDynamicSharedMemorySize, SM_STD);
    cudaFuncSetAttribute(snn_hmma<false, false, false>, cudaFuncAttributeMaxDynamicSharedMemorySize, SM_STD);
    cudaFuncSetAttribute(snn_hmma<false, false, true >, cudaFuncAttributeMaxDynamicSharedMemorySize, SM_STD);

    prep_all<<<2048, 256>>>(W1, W2, x, w1h, w1l, w1hu, w2h, w2l, xh, xl, xhs);

    dim3 blk(256);
    dim3 g1(DIM_H1 / 128, BATCH / 128);   // (16, 32)
    dim3 g2(DIM_H2 / 128, BATCH / 128);   // (8, 32)

    // t = 0 (mem starts at zero)
    snn_hmma<true, true, false><<<g1, blk, SM_TZ>>>(
        xh, xhs, xl, w1hu, w1l, b1, m1, s1, nullptr, DIM_H1, DIM_D);
    snn_hmma<false, true, true><<<g2, blk, SM_STD>>>(
        s1, nullptr, nullptr, w2h, w2l, b2, m2, s2, spk, DIM_H2, DIM_H1);

    for (int t = 1; t < NUM_STEPS; t++) {
        snn_hmma<false, false, false><<<g1, blk, SM_STD>>>(
            s2, nullptr, nullptr, w1h, w1l, b1, m1, s1, nullptr, DIM_H1, DIM_D);
        snn_hmma<false, false, true><<<g2, blk, SM_STD>>>(
            s1, nullptr, nullptr, w2h, w2l, b2, m2, s2, spk, DIM_H2, DIM_H1);
    }

    snn_readout<<<BATCH / 4, blk>>>(spk, Wo, bo, out);
}